// round 4
// baseline (speedup 1.0000x reference)
#include <cuda_runtime.h>
#include <cstdint>

// Problem constants
#define BATCH   256
#define N0      4096
#define N1      4096
#define N2      4096
#define N3      1024

#define ROWS_PER_BLOCK 8
#define NB_W1 (N0 / ROWS_PER_BLOCK)
#define NB_W2 (N1 / ROWS_PER_BLOCK)
#define NB_W3 (N2 / ROWS_PER_BLOCK)

#define GROUPS  64    // batch groups of 4 (4x16-bit packed in u64)
#define SPLITS  4     // source splits per group
#define SRC_PER_SPLIT (N0 / SPLITS)   // 1024

// Routing tables as u16 (indices < 4096), 16B-aligned for uint4 staging.
__device__ __align__(16) unsigned short g_d1[N0];
__device__ __align__(16) unsigned short g_d2[N1];
__device__ __align__(16) unsigned short g_d3[N2];

// Packed partial histograms: [group][bin], 4 batches x 16-bit fields.
// Zero at module load; convert_kernel re-zeros after reading, so every
// graph replay (and the correctness run) starts from zeros.
__device__ unsigned long long g_scratch[GROUPS * N3];

// ---------------------------------------------------------------------------
// Row argmax, warp per row, 8x-unrolled float4 loads.
// First-occurrence semantics (jnp.argmax).
// ---------------------------------------------------------------------------
__device__ __forceinline__ void argmax_row(const float* __restrict__ W,
                                           int row, int n_cols, int lane,
                                           unsigned short* __restrict__ out_idx)
{
    const float4* __restrict__ Wr =
        reinterpret_cast<const float4*>(W + (size_t)row * n_cols);
    const int n4 = n_cols >> 2;

    float best = -__int_as_float(0x7f800000);  // -inf
    int   bidx = 0;

    for (int i = lane; i < n4; i += 256) {
        float4 v[8];
        #pragma unroll
        for (int u = 0; u < 8; ++u) v[u] = Wr[i + u * 32];

        float g = -__int_as_float(0x7f800000);
        #pragma unroll
        for (int u = 0; u < 8; ++u)
            g = fmaxf(g, fmaxf(fmaxf(v[u].x, v[u].y), fmaxf(v[u].z, v[u].w)));

        if (g > best) {
            best = g;
            int idx = 0;
            // descending scan: last surviving write = smallest matching index
            #pragma unroll
            for (int u = 7; u >= 0; --u) {
                int base = (i + u * 32) << 2;
                if (v[u].w == g) idx = base + 3;
                if (v[u].z == g) idx = base + 2;
                if (v[u].y == g) idx = base + 1;
                if (v[u].x == g) idx = base;
            }
            bidx = idx;
        }
    }

    #pragma unroll
    for (int off = 16; off > 0; off >>= 1) {
        float ov = __shfl_down_sync(0xffffffffu, best, off);
        int   oi = __shfl_down_sync(0xffffffffu, bidx, off);
        if (ov > best || (ov == best && oi < bidx)) { best = ov; bidx = oi; }
    }
    if (lane == 0) out_idx[row] = (unsigned short)bidx;
}

__global__ void __launch_bounds__(256) fused_argmax_kernel(
    const float* __restrict__ W1,
    const float* __restrict__ W2,
    const float* __restrict__ W3)
{
    const int warp = threadIdx.x >> 5;
    const int lane = threadIdx.x & 31;
    const int bid  = blockIdx.x;

    if (bid < NB_W1) {
        argmax_row(W1, bid * ROWS_PER_BLOCK + warp, N1, lane, g_d1);
    } else if (bid < NB_W1 + NB_W2) {
        argmax_row(W2, (bid - NB_W1) * ROWS_PER_BLOCK + warp, N2, lane, g_d2);
    } else {
        argmax_row(W3, (bid - NB_W1 - NB_W2) * ROWS_PER_BLOCK + warp, N3, lane, g_d3);
    }
}

// ---------------------------------------------------------------------------
// Scatter, 4 batches packed per u64 atomic.
// Block (g, p): batches [4g, 4g+4), sources [1024p, 1024p+1024).
// Counts are 0..7 and per-bin totals <= 4096*7 = 28672 < 2^16, so the four
// 16-bit fields never carry into each other. Atomic count: 1024/block.
// Partial histograms merge into g_scratch via global u64 atomics.
// ---------------------------------------------------------------------------
__global__ void __launch_bounds__(512) scatter_kernel(const int* __restrict__ x)
{
    __shared__ unsigned short t1[N0];
    __shared__ unsigned short t2[N1];
    __shared__ unsigned short t3[N2];
    __shared__ unsigned long long hist[N3];

    const int tid = threadIdx.x;
    const int g   = blockIdx.x & (GROUPS - 1);   // batch group
    const int p   = blockIdx.x >> 6;             // source split

    // Stage tables: 4096 u16 = 512 uint4 per table, one per thread.
    reinterpret_cast<uint4*>(t1)[tid] = reinterpret_cast<const uint4*>(g_d1)[tid];
    reinterpret_cast<uint4*>(t2)[tid] = reinterpret_cast<const uint4*>(g_d2)[tid];
    reinterpret_cast<uint4*>(t3)[tid] = reinterpret_cast<const uint4*>(g_d3)[tid];
    hist[tid]       = 0ull;
    hist[tid + 512] = 0ull;
    __syncthreads();

    // Each thread: 2 consecutive sources x 4 batches (int2 per batch, coalesced)
    const int s0 = p * SRC_PER_SPLIT + 2 * tid;
    int2 c0 = *reinterpret_cast<const int2*>(x + (size_t)(4 * g + 0) * N0 + s0);
    int2 c1 = *reinterpret_cast<const int2*>(x + (size_t)(4 * g + 1) * N0 + s0);
    int2 c2 = *reinterpret_cast<const int2*>(x + (size_t)(4 * g + 2) * N0 + s0);
    int2 c3 = *reinterpret_cast<const int2*>(x + (size_t)(4 * g + 3) * N0 + s0);

    int f0 = t3[t2[t1[s0]]];
    int f1 = t3[t2[t1[s0 + 1]]];

    unsigned long long v0 =
          (unsigned long long)(unsigned)c0.x
        | ((unsigned long long)(unsigned)c1.x << 16)
        | ((unsigned long long)(unsigned)c2.x << 32)
        | ((unsigned long long)(unsigned)c3.x << 48);
    unsigned long long v1 =
          (unsigned long long)(unsigned)c0.y
        | ((unsigned long long)(unsigned)c1.y << 16)
        | ((unsigned long long)(unsigned)c2.y << 32)
        | ((unsigned long long)(unsigned)c3.y << 48);

    if (v0) atomicAdd(&hist[f0], v0);
    if (v1) atomicAdd(&hist[f1], v1);

    __syncthreads();

    // Merge partials into global scratch (4 contributing blocks per address)
    unsigned long long h0 = hist[tid];
    unsigned long long h1 = hist[tid + 512];
    if (h0) atomicAdd(&g_scratch[g * N3 + tid],       h0);
    if (h1) atomicAdd(&g_scratch[g * N3 + tid + 512], h1);
}

// ---------------------------------------------------------------------------
// Unpack scratch -> float out, and re-zero scratch for the next replay.
// Block g handles group g: 1024 bins, 4 output rows.
// ---------------------------------------------------------------------------
__global__ void __launch_bounds__(1024) convert_kernel(float* __restrict__ out)
{
    const int g = blockIdx.x;
    const int j = threadIdx.x;

    unsigned long long v = g_scratch[g * N3 + j];
    g_scratch[g * N3 + j] = 0ull;

    float* __restrict__ ob = out + (size_t)(4 * g) * N3 + j;
    ob[0]      = (float)( v        & 0xFFFFull);
    ob[N3]     = (float)((v >> 16) & 0xFFFFull);
    ob[2 * N3] = (float)((v >> 32) & 0xFFFFull);
    ob[3 * N3] = (float)((v >> 48) & 0xFFFFull);
}

// ---------------------------------------------------------------------------
// Launch
//   d_in[0] = x  (int32,   [256, 4096])
//   d_in[1] = W1 (float32, [4096, 4096])
//   d_in[2] = W2 (float32, [4096, 4096])
//   d_in[3] = W3 (float32, [4096, 1024])
//   d_out   = float32 [256, 1024]
// ---------------------------------------------------------------------------
extern "C" void kernel_launch(void* const* d_in, const int* in_sizes, int n_in,
                              void* d_out, int out_size)
{
    const int*   x  = (const int*)  d_in[0];
    const float* W1 = (const float*)d_in[1];
    const float* W2 = (const float*)d_in[2];
    const float* W3 = (const float*)d_in[3];
    float* out = (float*)d_out;

    fused_argmax_kernel<<<NB_W1 + NB_W2 + NB_W3, 256>>>(W1, W2, W3);
    scatter_kernel<<<GROUPS * SPLITS, 512>>>(x);
    convert_kernel<<<GROUPS, 1024>>>(out);
}